// round 9
// baseline (speedup 1.0000x reference)
#include <cuda_runtime.h>
#include <cstddef>

// PathSampling — R9: persistent CTAs with a 224KB smem-resident prefix of the
// centrality table. Gathers with idx < S_PREFIX go to shared memory (cheap
// conflict wavefronts) instead of the L1tex LDG line-gather path; the rest
// stay as predicated __ldg. Selection/output logic identical to R6 (best).
//
//  paths      [n_node, 32, 8] int32
//  edge_ids   [n_node, 32, 7] int32
//  rand_lens  [n_node, 32]    int32
//  centrality [n_graph]       float32
//  out (float32): concat(paths_sel [n,8,8], edge_ids_sel [n,8,7]);
//  int->float exact (ids < 2^24; mask -> -1.0f).

#define N_PATH 32
#define L_PATH 8
#define K_SEL  8
#define E_PER  (L_PATH - 1)           // 7
#define E_TOT  (K_SEL * E_PER)        // 56

#define S_PREFIX   57344              // floats resident in smem (224 KB)
#define SMEM_BYTES (S_PREFIX * 4)
#define CTA_THREADS 1024

__global__ void __launch_bounds__(CTA_THREADS, 1) path_sampling_kernel(
    const int*   __restrict__ paths,
    const int*   __restrict__ edge_ids,
    const int*   __restrict__ rand_lens,
    const float* __restrict__ centrality,
    float*       __restrict__ out_paths,   // [n_node, 8, 8] float32
    float*       __restrict__ out_edges,   // [n_node, 8, 7] float32 or nullptr
    int n_node,
    int s_prefix)                          // min(S_PREFIX, n_graph)
{
    extern __shared__ float sh_tab[];

    // cooperative load of the table prefix (coalesced, L2-hot after wave 1)
    for (int i = threadIdx.x; i < s_prefix; i += CTA_THREADS) {
        sh_tab[i] = __ldg(centrality + i);
    }
    __syncthreads();

    const int wid   = threadIdx.x >> 5;          // 0..31
    const int lane  = threadIdx.x & 31;
    const int gwarp = blockIdx.x * (CTA_THREADS / 32) + wid;
    const int wstep = gridDim.x * (CTA_THREADS / 32);

    for (int node = gwarp; node < n_node; node += wstep) {
        // rand_len for this lane's path (coalesced 128B per warp, read-once)
        const int rl = __ldcs(rand_lens + (size_t)node * N_PATH + lane);

        // This lane's 8 path node-ids: 2 x LDG.128.CS, coalesced, read-once
        const int4* p4 = reinterpret_cast<const int4*>(
            paths + (size_t)node * N_PATH * L_PATH);
        int4 a = __ldcs(p4 + lane * 2);
        int4 b = __ldcs(p4 + lane * 2 + 1);
        int pj[L_PATH] = {a.x, a.y, a.z, a.w, b.x, b.y, b.z, b.w};

        // Predicated gathers: smem if idx in prefix, else global. Masked
        // positions contribute exactly +0.0f (same as zero-padded reference).
        float c[L_PATH];
#pragma unroll
        for (int j = 0; j < L_PATH; j++) {
            float v = 0.0f;
            if (j <= rl) {
                int idx = pj[j];
                v = (idx < s_prefix) ? sh_tab[idx] : __ldg(centrality + idx);
            }
            c[j] = v;
        }
        float s = 0.0f;
#pragma unroll
        for (int j = 0; j < L_PATH; j++) s += c[j];   // matches jnp.sum order

        // Mask the path values we will emit
#pragma unroll
        for (int j = 0; j < L_PATH; j++) {
            if (j > rl) pj[j] = -1;
        }

        // Stable rank: #{k : s_k > s OR (s_k == s AND k < lane)} — lax.top_k
        // tie-break; ranks are a permutation of 0..31.
        int rank = 0;
#pragma unroll
        for (int k = 0; k < 32; k++) {
            float sk = __shfl_sync(0xffffffffu, s, k);
            rank += (sk > s) || (sk == s && k < lane);
        }

        // rank -> lane map for the 8 winners, 5 bits each in a uint64
        unsigned long long src_packed = 0ull;
#pragma unroll
        for (int r = 0; r < K_SEL; r++) {
            unsigned bal = __ballot_sync(0xffffffffu, rank == r);
            src_packed |= (unsigned long long)(__ffs(bal) - 1) << (5 * r);
        }

        // Winner lanes write their own masked path row (2 x STG.128.CS;
        // the 8 winners cover a contiguous 256B block per node).
        if (rank < K_SEL) {
            float4* op = reinterpret_cast<float4*>(
                out_paths + ((size_t)node * K_SEL + rank) * L_PATH);
            __stcs(op,     make_float4((float)pj[0], (float)pj[1],
                                       (float)pj[2], (float)pj[3]));
            __stcs(op + 1, make_float4((float)pj[4], (float)pj[5],
                                       (float)pj[6], (float)pj[7]));
        }

        // Cooperative edge copy: 32 lanes move the 56 selected edge ints.
        // Sources in one contiguous 896B block; destination 224B contiguous.
        if (out_edges != nullptr) {
            const int* eb = edge_ids + (size_t)node * N_PATH * E_PER;
            float*     ew = out_edges + (size_t)node * E_TOT;
#pragma unroll
            for (int t = lane; t < E_TOT; t += 32) {
                int w = t / E_PER;
                int j = t - w * E_PER;
                int srcl = (int)((src_packed >> (5 * w)) & 31ull);
                __stcs(ew + t, (float)__ldcs(eb + srcl * E_PER + j));
            }
        }
    }
}

extern "C" void kernel_launch(void* const* d_in, const int* in_sizes, int n_in,
                              void* d_out, int out_size)
{
    // ---- bind inputs by size (immune to metadata ordering) ----
    const void* ptr[8];
    long long   sz[8];
    int m = n_in > 8 ? 8 : n_in;
    for (int i = 0; i < m; i++) { ptr[i] = d_in[i]; sz[i] = in_sizes[i]; }

    int i_paths = 0;
    for (int i = 1; i < m; i++) if (sz[i] > sz[i_paths]) i_paths = i;
    int i_edges = -1;
    for (int i = 0; i < m; i++) {
        if (i == i_paths) continue;
        if (i_edges < 0 || sz[i] > sz[i_edges]) i_edges = i;
    }

    const long long oo = (long long)out_size;
    const long long np_sz = sz[i_paths];
    long long n_node_ll;
    bool has_edges;
    if (oo % (K_SEL * (2 * L_PATH - 1)) == 0 && np_sz == (oo / 120) * 256) {
        n_node_ll = oo / 120;           // both outputs concatenated in d_out
        has_edges = true;
    } else if (oo % (K_SEL * L_PATH) == 0 && np_sz == (oo / 64) * 256) {
        n_node_ll = oo / 64;            // only paths_sel fits in d_out
        has_edges = false;
    } else {
        n_node_ll = np_sz / (N_PATH * L_PATH);
        has_edges = (oo >= n_node_ll * 120);
    }

    int i_lens = -1, i_cent = -1;
    for (int i = 0; i < m; i++) {
        if (i == i_paths || i == i_edges) continue;
        if (sz[i] == n_node_ll * N_PATH) i_lens = i;
    }
    for (int i = 0; i < m; i++) {
        if (i == i_paths || i == i_edges || i == i_lens) continue;
        if (sz[i] > 4) i_cent = i;
    }
    if (i_lens < 0) i_lens = 2;
    if (i_cent < 0) i_cent = 3;

    const int*   paths      = (const int*)  ptr[i_paths];
    const int*   edge_ids   = (const int*)  ptr[i_edges];
    const int*   rand_lens  = (const int*)  ptr[i_lens];
    const float* centrality = (const float*)ptr[i_cent];
    const int    n_node     = (int)n_node_ll;
    const long long n_graph = sz[i_cent];
    const int    s_prefix   = (int)(n_graph < S_PREFIX ? n_graph : S_PREFIX);

    float* out_paths = (float*)d_out;
    float* out_edges = has_edges ? out_paths + (size_t)n_node * K_SEL * L_PATH
                                 : nullptr;

    // opt-in to 224KB dynamic smem (idempotent; capture-safe, not an alloc)
    cudaFuncSetAttribute(path_sampling_kernel,
                         cudaFuncAttributeMaxDynamicSharedMemorySize,
                         SMEM_BYTES);

    int dev = 0, sms = 148;
    cudaGetDevice(&dev);
    cudaDeviceGetAttribute(&sms, cudaDevAttrMultiProcessorCount, dev);

    path_sampling_kernel<<<sms, CTA_THREADS, SMEM_BYTES>>>(
        paths, edge_ids, rand_lens, centrality,
        out_paths, out_edges, n_node, s_prefix);
}